// round 2
// baseline (speedup 1.0000x reference)
#include <cuda_runtime.h>

#define N_SRC     100000
#define N_NODES   1000000
#define N_NEIGH   20
#define RAW_DIM   256
#define HID       128
#define MSG       128
#define NEIGH_DIM 128

#define TM      16     // rows per block
#define THREADS 128    // one thread per output column

// Flag: 1 if neighbors buffer is int64, 0 if int32.
__device__ int g_is64;

__global__ void detect_idx_kernel(const long long* __restrict__ n) {
    if (threadIdx.x == 0 && blockIdx.x == 0) {
        int is64 = 1;
        for (int i = 0; i < 64; i++) {
            long long v = n[i];                    // safe: bytes [0,512) exist either way
            if (v < 0 || v >= (long long)N_NODES) { is64 = 0; break; }
        }
        g_is64 = is64;
    }
}

__global__ __launch_bounds__(THREADS)
void fused_neigh_msg_kernel(
    const float* __restrict__ raw,      // [N_SRC, 256]
    const void*  __restrict__ neigh,    // [N_SRC, 20] int64 or int32
    const float* __restrict__ memory,   // [N_NODES, 128]
    const float* __restrict__ W1,       // [256, 128]
    const float* __restrict__ b1,       // [128]
    const float* __restrict__ W2,       // [128, 128]
    const float* __restrict__ b2,       // [128]
    const float* __restrict__ Wn,       // [128, 128]
    const float* __restrict__ bn,       // [128]
    float*       __restrict__ out)      // [N_SRC, 128]
{
    __shared__ float sraw[TM][RAW_DIM];       // 16 KB
    __shared__ float sh  [TM][HID];           //  8 KB
    __shared__ float sagg[TM][NEIGH_DIM];     //  8 KB
    __shared__ int   sneigh[TM][N_NEIGH];     // 1.25 KB (indices < 1e6 fit in int)
    __shared__ int   s_is64;

    const int tid  = threadIdx.x;
    const int col  = tid;                     // 0..127
    const int row0 = blockIdx.x * TM;

    if (tid == 0) s_is64 = g_is64;

    // ---- load raw tile [TM,256] via float4, coalesced ----
    {
        const float4* rawv = (const float4*)raw;
        const int nvec = TM * (RAW_DIM / 4);  // 1024
        for (int i = tid; i < nvec; i += THREADS) {
            int r = i / (RAW_DIM / 4);
            int c = i % (RAW_DIM / 4);
            float4 v;
            if (row0 + r < N_SRC)
                v = rawv[(row0 + r) * (RAW_DIM / 4) + c];
            else
                v = make_float4(0.f, 0.f, 0.f, 0.f);
            ((float4*)&sraw[r][0])[c] = v;
        }
    }
    __syncthreads();   // s_is64 + raw tile visible

    // ---- load neighbor indices (uniform branch on dtype) ----
    if (s_is64) {
        const long long* n64 = (const long long*)neigh;
        for (int i = tid; i < TM * N_NEIGH; i += THREADS) {
            int r = i / N_NEIGH, j = i % N_NEIGH;
            sneigh[r][j] = (row0 + r < N_SRC) ? (int)n64[(row0 + r) * N_NEIGH + j] : 0;
        }
    } else {
        const int* n32 = (const int*)neigh;
        for (int i = tid; i < TM * N_NEIGH; i += THREADS) {
            int r = i / N_NEIGH, j = i % N_NEIGH;
            sneigh[r][j] = (row0 + r < N_SRC) ? n32[(row0 + r) * N_NEIGH + j] : 0;
        }
    }
    __syncthreads();

    // ---- phase 1: h = relu(raw @ W1 + b1), thread owns column `col` ----
    {
        float acc[TM];
        const float bv = b1[col];
        #pragma unroll
        for (int r = 0; r < TM; r++) acc[r] = bv;

        for (int k = 0; k < RAW_DIM; k += 4) {
            const float w0 = W1[(k + 0) * HID + col];
            const float w1 = W1[(k + 1) * HID + col];
            const float w2 = W1[(k + 2) * HID + col];
            const float w3 = W1[(k + 3) * HID + col];
            #pragma unroll
            for (int r = 0; r < TM; r++) {
                float4 v = *(const float4*)&sraw[r][k];   // warp-broadcast, conflict-free
                acc[r] = fmaf(v.x, w0, acc[r]);
                acc[r] = fmaf(v.y, w1, acc[r]);
                acc[r] = fmaf(v.z, w2, acc[r]);
                acc[r] = fmaf(v.w, w3, acc[r]);
            }
        }
        #pragma unroll
        for (int r = 0; r < TM; r++) sh[r][col] = fmaxf(acc[r], 0.f);
    }
    __syncthreads();

    // ---- phase 2: a = relu(h @ W2 + b2), kept in registers ----
    float a_r[TM];
    {
        const float bv = b2[col];
        #pragma unroll
        for (int r = 0; r < TM; r++) a_r[r] = bv;

        for (int k = 0; k < HID; k += 4) {
            const float w0 = W2[(k + 0) * MSG + col];
            const float w1 = W2[(k + 1) * MSG + col];
            const float w2 = W2[(k + 2) * MSG + col];
            const float w3 = W2[(k + 3) * MSG + col];
            #pragma unroll
            for (int r = 0; r < TM; r++) {
                float4 v = *(const float4*)&sh[r][k];
                a_r[r] = fmaf(v.x, w0, a_r[r]);
                a_r[r] = fmaf(v.y, w1, a_r[r]);
                a_r[r] = fmaf(v.z, w2, a_r[r]);
                a_r[r] = fmaf(v.w, w3, a_r[r]);
            }
        }
        #pragma unroll
        for (int r = 0; r < TM; r++) a_r[r] = fmaxf(a_r[r], 0.f);
    }

    // ---- phase 3: gather + mean over 20 neighbors (coalesced 512B rows) ----
    {
        const float inv = 1.0f / (float)N_NEIGH;
        #pragma unroll 1
        for (int r = 0; r < TM; r++) {
            float s = 0.f;
            #pragma unroll
            for (int j = 0; j < N_NEIGH; j++) {
                int node = sneigh[r][j];
                s += __ldg(&memory[node * NEIGH_DIM + col]);
            }
            sagg[r][col] = s * inv;
        }
    }
    __syncthreads();

    // ---- phase 4: b = relu(agg @ Wn + bn); out = a + b ----
    {
        const float bv = bn[col];
        float acc[TM];
        #pragma unroll
        for (int r = 0; r < TM; r++) acc[r] = bv;

        for (int k = 0; k < NEIGH_DIM; k += 4) {
            const float w0 = Wn[(k + 0) * MSG + col];
            const float w1 = Wn[(k + 1) * MSG + col];
            const float w2 = Wn[(k + 2) * MSG + col];
            const float w3 = Wn[(k + 3) * MSG + col];
            #pragma unroll
            for (int r = 0; r < TM; r++) {
                float4 v = *(const float4*)&sagg[r][k];
                acc[r] = fmaf(v.x, w0, acc[r]);
                acc[r] = fmaf(v.y, w1, acc[r]);
                acc[r] = fmaf(v.z, w2, acc[r]);
                acc[r] = fmaf(v.w, w3, acc[r]);
            }
        }
        #pragma unroll
        for (int r = 0; r < TM; r++) {
            int row = row0 + r;
            if (row < N_SRC)
                out[row * MSG + col] = a_r[r] + fmaxf(acc[r], 0.f);
        }
    }
}

extern "C" void kernel_launch(void* const* d_in, const int* in_sizes, int n_in,
                              void* d_out, int out_size) {
    const float* raw    = (const float*)d_in[0];
    const void*  neigh  = (const void*) d_in[1];
    const float* memory = (const float*)d_in[2];
    const float* W1     = (const float*)d_in[3];
    const float* b1     = (const float*)d_in[4];
    const float* W2     = (const float*)d_in[5];
    const float* b2     = (const float*)d_in[6];
    const float* Wn     = (const float*)d_in[7];
    const float* bn     = (const float*)d_in[8];
    float* out          = (float*)d_out;

    detect_idx_kernel<<<1, 32>>>((const long long*)neigh);

    int nblocks = (N_SRC + TM - 1) / TM;   // 6250
    fused_neigh_msg_kernel<<<nblocks, THREADS>>>(
        raw, neigh, memory, W1, b1, W2, b2, Wn, bn, out);
}

// round 4
// speedup vs baseline: 1.2314x; 1.2314x over previous
#include <cuda_runtime.h>
#include <cuda_bf16.h>
#include <cstdint>

#define N_SRC     100000
#define N_NODES   1000000
#define N_NEIGH   20
#define RAW_DIM   256
#define MSG       128

#define TM        128
#define THREADS   256

// bf16 tiles padded to 136 elems/row (272 B = 17*16B: ldmatrix conflict-free)
#define TSTRIDE   136
#define TILE_B    (128 * TSTRIDE * 2)      // 34816

#define OFF_AH    0
#define OFF_AL    (OFF_AH + TILE_B)        // 34816
#define OFF_BH    (OFF_AL + TILE_B)        // 69632
#define OFF_BL    (OFF_BH + TILE_B)        // 104448
#define OFF_STG   (OFF_BL + TILE_B)        // 139264  fp32 [64][256] = 65536
#define OFF_NEI   (OFF_STG + 65536)        // 204800  int [128][20] = 10240
#define OFF_B1S   (OFF_NEI + 10240)        // 215040
#define OFF_B2S   (OFF_B1S + 512)
#define OFF_BNS   (OFF_B2S + 512)
#define OFF_IS64  (OFF_BNS + 512)          // 216576
#define SMEM_REQ  (OFF_IS64 + 16)          // 216592

__device__ int g_is64;

__global__ void detect_idx_kernel(const long long* __restrict__ n) {
    if (threadIdx.x == 0 && blockIdx.x == 0) {
        int is64 = 1;
        for (int i = 0; i < 64; i++) {
            long long v = n[i];
            if (v < 0 || v >= (long long)N_NODES) { is64 = 0; break; }
        }
        g_is64 = is64;
    }
}

__device__ __forceinline__ uint32_t smem_u32(const void* p) {
    uint32_t a;
    asm("{ .reg .u64 t; cvta.to.shared.u64 t, %1; cvt.u32.u64 %0, t; }" : "=r"(a) : "l"(p));
    return a;
}

#define LDSM_X4(r, addr) \
    asm volatile("ldmatrix.sync.aligned.m8n8.x4.shared.b16 {%0,%1,%2,%3}, [%4];" \
        : "=r"((r)[0]), "=r"((r)[1]), "=r"((r)[2]), "=r"((r)[3]) : "r"(addr))

#define LDSM_X4T(r, addr) \
    asm volatile("ldmatrix.sync.aligned.m8n8.x4.trans.shared.b16 {%0,%1,%2,%3}, [%4];" \
        : "=r"((r)[0]), "=r"((r)[1]), "=r"((r)[2]), "=r"((r)[3]) : "r"(addr))

#define MMA16816(ac, a, b0, b1) \
    asm volatile("mma.sync.aligned.m16n8k16.row.col.f32.bf16.bf16.f32 " \
        "{%0,%1,%2,%3}, {%4,%5,%6,%7}, {%8,%9}, {%0,%1,%2,%3};" \
        : "+f"((ac)[0]), "+f"((ac)[1]), "+f"((ac)[2]), "+f"((ac)[3]) \
        : "r"((a)[0]), "r"((a)[1]), "r"((a)[2]), "r"((a)[3]), "r"(b0), "r"(b1))

__device__ __forceinline__ unsigned short bf_hi(float x) {
    return __bfloat16_as_ushort(__float2bfloat16(x));
}
__device__ __forceinline__ unsigned short bf_lo(float x) {
    __nv_bfloat16 h = __float2bfloat16(x);
    return __bfloat16_as_ushort(__float2bfloat16(x - __bfloat162float(h)));
}
__device__ __forceinline__ uint32_t pack2(unsigned short a, unsigned short b) {
    return (uint32_t)a | ((uint32_t)b << 16);
}

// ---- K=128 triple product: acc += Ah@Bh + Al@Bh + Ah@Bl  (error-compensated) ----
__device__ __forceinline__ void run_product(
    float acc[2][8][4], uint32_t sAh, uint32_t sAl, uint32_t sBh, uint32_t sBl,
    int lane, int r0, int c0)
{
    const int arow = lane & 15;
    const int aka  = (lane >> 4) << 3;          // +8 k for upper half-warp
    const int bk   = (lane & 7) + ((lane >> 3) & 1) * 8;
    const int bn   = ((lane >> 4) & 1) * 8;
    #pragma unroll
    for (int ks = 0; ks < 8; ks++) {
        const int k0 = ks * 16;
        uint32_t ah[2][4], al[2][4], bh[4][4], bl[4][4];
        #pragma unroll
        for (int mt = 0; mt < 2; mt++) {
            uint32_t off = (uint32_t)((r0 + mt * 16 + arow) * (TSTRIDE * 2) + (k0 + aka) * 2);
            LDSM_X4(ah[mt], sAh + off);
            LDSM_X4(al[mt], sAl + off);
        }
        #pragma unroll
        for (int ng = 0; ng < 4; ng++) {
            uint32_t off = (uint32_t)((k0 + bk) * (TSTRIDE * 2) + (c0 + ng * 16 + bn) * 2);
            LDSM_X4T(bh[ng], sBh + off);
            LDSM_X4T(bl[ng], sBl + off);
        }
        #pragma unroll
        for (int mt = 0; mt < 2; mt++) {
            #pragma unroll
            for (int nt = 0; nt < 8; nt++) {
                const int ng = nt >> 1, s2 = (nt & 1) * 2;
                MMA16816(acc[mt][nt], ah[mt], bh[ng][s2], bh[ng][s2 + 1]);
                MMA16816(acc[mt][nt], al[mt], bh[ng][s2], bh[ng][s2 + 1]);
                MMA16816(acc[mt][nt], ah[mt], bl[ng][s2], bl[ng][s2 + 1]);
            }
        }
    }
}

// A tile loader: raw[row0+m][k0 .. k0+127] -> hi/lo bf16 tiles, coalesced
__device__ __forceinline__ void load_A_raw(char* sm, const float* __restrict__ raw,
                                           int row0, int valid, int k0) {
    const int tid = threadIdx.x;
    #pragma unroll 2
    for (int i = tid; i < 128 * 32; i += THREADS) {
        int m  = i >> 5;
        int k4 = (i & 31) << 2;
        float4 v = make_float4(0.f, 0.f, 0.f, 0.f);
        if (m < valid)
            v = *(const float4*)&raw[(size_t)(row0 + m) * RAW_DIM + k0 + k4];
        uint2 hp = make_uint2(pack2(bf_hi(v.x), bf_hi(v.y)), pack2(bf_hi(v.z), bf_hi(v.w)));
        uint2 lp = make_uint2(pack2(bf_lo(v.x), bf_lo(v.y)), pack2(bf_lo(v.z), bf_lo(v.w)));
        *(uint2*)(sm + OFF_AH + m * (TSTRIDE * 2) + k4 * 2) = hp;
        *(uint2*)(sm + OFF_AL + m * (TSTRIDE * 2) + k4 * 2) = lp;
    }
}

// B tile loader: W[k0+k][0..127] row-major -> hi/lo bf16 tiles, coalesced
__device__ __forceinline__ void load_B_w(char* sm, const float* __restrict__ W, int k0) {
    const int tid = threadIdx.x;
    #pragma unroll 2
    for (int i = tid; i < 128 * 32; i += THREADS) {
        int k  = i >> 5;
        int n4 = (i & 31) << 2;
        float4 v = *(const float4*)&W[(size_t)(k0 + k) * 128 + n4];
        uint2 hp = make_uint2(pack2(bf_hi(v.x), bf_hi(v.y)), pack2(bf_hi(v.z), bf_hi(v.w)));
        uint2 lp = make_uint2(pack2(bf_lo(v.x), bf_lo(v.y)), pack2(bf_lo(v.z), bf_lo(v.w)));
        *(uint2*)(sm + OFF_BH + k * (TSTRIDE * 2) + n4 * 2) = hp;
        *(uint2*)(sm + OFF_BL + k * (TSTRIDE * 2) + n4 * 2) = lp;
    }
}

extern __shared__ char sm[];

__global__ __launch_bounds__(THREADS, 1)
void fused_hmma_kernel(
    const float* __restrict__ raw,
    const void*  __restrict__ neigh,
    const float* __restrict__ memory,
    const float* __restrict__ W1, const float* __restrict__ b1,
    const float* __restrict__ W2, const float* __restrict__ b2,
    const float* __restrict__ Wn, const float* __restrict__ bn,
    float*       __restrict__ out)
{
    const uint32_t smb = smem_u32(sm);
    const int tid  = threadIdx.x;
    const int lane = tid & 31;
    const int wid  = tid >> 5;
    const int r0   = (wid >> 1) * 32;     // warp row base
    const int c0   = (wid & 1) * 64;      // warp col base
    const int row0 = blockIdx.x * TM;
    const int valid = min(TM, N_SRC - row0);

    if (tid == 0) *(int*)(sm + OFF_IS64) = g_is64;
    if (tid < 128) {
        ((float*)(sm + OFF_B1S))[tid] = b1[tid];
        ((float*)(sm + OFF_B2S))[tid] = b2[tid];
        ((float*)(sm + OFF_BNS))[tid] = bn[tid];
    }
    __syncthreads();

    // ---- neighbor indices -> smem ----
    {
        int is64 = *(volatile int*)(sm + OFF_IS64);
        int* nbw = (int*)(sm + OFF_NEI);
        if (is64) {
            const long long* p = (const long long*)neigh;
            for (int i = tid; i < TM * N_NEIGH; i += THREADS) {
                int r = i / N_NEIGH, j = i - r * N_NEIGH;
                nbw[i] = (r < valid) ? (int)p[(size_t)(row0 + r) * N_NEIGH + j] : 0;
            }
        } else {
            const int* p = (const int*)neigh;
            for (int i = tid; i < TM * N_NEIGH; i += THREADS) {
                int r = i / N_NEIGH, j = i - r * N_NEIGH;
                nbw[i] = (r < valid) ? p[(size_t)(row0 + r) * N_NEIGH + j] : 0;
            }
        }
    }
    __syncthreads();

    // ---- L2 prefetch of all gather sectors (overlaps GEMM1/GEMM2) ----
    {
        const int* nb = (const int*)(sm + OFF_NEI);
        for (int p = tid; p < TM * N_NEIGH * 4; p += THREADS) {
            int node = nb[p >> 2];
            const char* ptr = (const char*)memory + (size_t)node * 512 + (size_t)(p & 3) * 128;
            asm volatile("prefetch.global.L2 [%0];" :: "l"(ptr));
        }
    }

    const uint32_t AH = smb + OFF_AH, AL = smb + OFF_AL;
    const uint32_t BH = smb + OFF_BH, BL = smb + OFF_BL;

    float acc[2][8][4];
    #pragma unroll
    for (int mt = 0; mt < 2; mt++)
        #pragma unroll
        for (int nt = 0; nt < 8; nt++)
            #pragma unroll
            for (int e = 0; e < 4; e++) acc[mt][nt][e] = 0.f;

    // ================= GEMM1: C1 = raw @ W1 (K=256, two chunks) =================
    load_A_raw(sm, raw, row0, valid, 0);
    load_B_w(sm, W1, 0);
    __syncthreads();
    run_product(acc, AH, AL, BH, BL, lane, r0, c0);
    __syncthreads();

    load_A_raw(sm, raw, row0, valid, 128);
    load_B_w(sm, W1, 128);
    __syncthreads();
    run_product(acc, AH, AL, BH, BL, lane, r0, c0);
    __syncthreads();

    // ---- epilogue 1: h = relu(C1 + b1) -> A hi/lo tiles ----
    {
        const float* sb1 = (const float*)(sm + OFF_B1S);
        const int qr = lane >> 2, qc = (lane & 3) * 2;
        #pragma unroll
        for (int mt = 0; mt < 2; mt++) {
            #pragma unroll
            for (int nt = 0; nt < 8; nt++) {
                int R = r0 + mt * 16 + qr;
                int C = c0 + nt * 8 + qc;
                float v0 = fmaxf(acc[mt][nt][0] + sb1[C],     0.f);
                float v1 = fmaxf(acc[mt][nt][1] + sb1[C + 1], 0.f);
                float v2 = fmaxf(acc[mt][nt][2] + sb1[C],     0.f);
                float v3 = fmaxf(acc[mt][nt][3] + sb1[C + 1], 0.f);
                *(uint32_t*)(sm + OFF_AH + R * (TSTRIDE * 2) + C * 2)       = pack2(bf_hi(v0), bf_hi(v1));
                *(uint32_t*)(sm + OFF_AL + R * (TSTRIDE * 2) + C * 2)       = pack2(bf_lo(v0), bf_lo(v1));
                *(uint32_t*)(sm + OFF_AH + (R + 8) * (TSTRIDE * 2) + C * 2) = pack2(bf_hi(v2), bf_hi(v3));
                *(uint32_t*)(sm + OFF_AL + (R + 8) * (TSTRIDE * 2) + C * 2) = pack2(bf_lo(v2), bf_lo(v3));
                acc[mt][nt][0] = acc[mt][nt][1] = acc[mt][nt][2] = acc[mt][nt][3] = 0.f;
            }
        }
    }
    load_B_w(sm, W2, 0);
    __syncthreads();

    // ================= GEMM2: C2 = h @ W2 (K=128) =================
    run_product(acc, AH, AL, BH, BL, lane, r0, c0);
    __syncthreads();

    // ---- stage a = relu(C2 + b2) into private smem slots; zero acc ----
    {
        const float* sb2 = (const float*)(sm + OFF_B2S);
        float* stg = (float*)(sm + OFF_STG);
        const int qc = (lane & 3) * 2;
        #pragma unroll
        for (int mt = 0; mt < 2; mt++) {
            #pragma unroll
            for (int nt = 0; nt < 8; nt++) {
                int C = c0 + nt * 8 + qc;
                int base = (mt * 32 + nt * 4) * THREADS + tid;
                stg[base]               = fmaxf(acc[mt][nt][0] + sb2[C],     0.f);
                stg[base + THREADS]     = fmaxf(acc[mt][nt][1] + sb2[C + 1], 0.f);
                stg[base + 2 * THREADS] = fmaxf(acc[mt][nt][2] + sb2[C],     0.f);
                stg[base + 3 * THREADS] = fmaxf(acc[mt][nt][3] + sb2[C + 1], 0.f);
                acc[mt][nt][0] = acc[mt][nt][1] = acc[mt][nt][2] = acc[mt][nt][3] = 0.f;
            }
        }
    }

    // ---- gather + mean -> A hi/lo tiles (mostly L2 hits thanks to prefetch) ----
    {
        const int c = tid & 127;
        const int half = tid >> 7;
        const int* nb = (const int*)(sm + OFF_NEI);
        for (int mm = half; mm < TM; mm += 2) {
            float s = 0.f;
            #pragma unroll
            for (int j = 0; j < N_NEIGH; j++) {
                int nd = nb[mm * N_NEIGH + j];
                s += __ldg(&memory[(size_t)nd * 128 + c]);
            }
            s *= (1.0f / N_NEIGH);
            *(__nv_bfloat16*)(sm + OFF_AH + mm * (TSTRIDE * 2) + c * 2) =
                __ushort_as_bfloat16(bf_hi(s));
            *(__nv_bfloat16*)(sm + OFF_AL + mm * (TSTRIDE * 2) + c * 2) =
                __ushort_as_bfloat16(bf_lo(s));
        }
    }
    load_B_w(sm, Wn, 0);
    __syncthreads();

    // ================= GEMM3: C3 = agg @ Wn (K=128) =================
    run_product(acc, AH, AL, BH, BL, lane, r0, c0);

    // ---- final: out = a + relu(C3 + bn) ----
    {
        const float* sbn = (const float*)(sm + OFF_BNS);
        const float* stg = (const float*)(sm + OFF_STG);
        const int qr = lane >> 2, qc = (lane & 3) * 2;
        #pragma unroll
        for (int mt = 0; mt < 2; mt++) {
            #pragma unroll
            for (int nt = 0; nt < 8; nt++) {
                int R = r0 + mt * 16 + qr;
                int C = c0 + nt * 8 + qc;
                int base = (mt * 32 + nt * 4) * THREADS + tid;
                float o0 = stg[base]               + fmaxf(acc[mt][nt][0] + sbn[C],     0.f);
                float o1 = stg[base + THREADS]     + fmaxf(acc[mt][nt][1] + sbn[C + 1], 0.f);
                float o2 = stg[base + 2 * THREADS] + fmaxf(acc[mt][nt][2] + sbn[C],     0.f);
                float o3 = stg[base + 3 * THREADS] + fmaxf(acc[mt][nt][3] + sbn[C + 1], 0.f);
                if (R < valid)
                    *(float2*)&out[(size_t)(row0 + R) * MSG + C] = make_float2(o0, o1);
                if (R + 8 < valid)
                    *(float2*)&out[(size_t)(row0 + R + 8) * MSG + C] = make_float2(o2, o3);
            }
        }
    }
}

extern "C" void kernel_launch(void* const* d_in, const int* in_sizes, int n_in,
                              void* d_out, int out_size) {
    const float* raw    = (const float*)d_in[0];
    const void*  neigh  = (const void*) d_in[1];
    const float* memory = (const float*)d_in[2];
    const float* W1     = (const float*)d_in[3];
    const float* b1     = (const float*)d_in[4];
    const float* W2     = (const float*)d_in[5];
    const float* b2     = (const float*)d_in[6];
    const float* Wn     = (const float*)d_in[7];
    const float* bn     = (const float*)d_in[8];
    float* out          = (float*)d_out;

    cudaFuncSetAttribute(fused_hmma_kernel,
                         cudaFuncAttributeMaxDynamicSharedMemorySize, SMEM_REQ);

    detect_idx_kernel<<<1, 32>>>((const long long*)neigh);

    int nblocks = (N_SRC + TM - 1) / TM;   // 782
    fused_hmma_kernel<<<nblocks, THREADS, SMEM_REQ>>>(
        raw, neigh, memory, W1, b1, W2, b2, Wn, bn, out);
}

// round 5
// speedup vs baseline: 1.8799x; 1.5267x over previous
#include <cuda_runtime.h>
#include <cuda_bf16.h>
#include <cstdint>

#define N_SRC     100000
#define N_NODES   1000000
#define N_NEIGH   20
#define RAW_DIM   256
#define MSG       128

#define TM        64
#define THREADS   384          // 8 MMA warps + 4 gather warps
#define NMMA      256

#define TSTRIDE   136          // bf16 elems per tile row (272 B = 17*16B)
#define ROWB      (TSTRIDE * 2)

#define OFF_AH    0                         // 64 x 136 bf16 = 17408
#define OFF_AL    17408
#define OFF_BH    34816                     // 128 x 136 bf16 = 34816
#define OFF_BL    69632
#define OFF_STG   104448                    // fp32 stage for 'a': 32768
#define OFF_NEI   137216                    // int [64][20] = 5120
#define OFF_B1S   142336
#define OFF_B2S   142848
#define OFF_BNS   143360
#define OFF_IS64  143872
#define SMEM_REQ  143888

__device__ int g_is64;

__global__ void detect_idx_kernel(const long long* __restrict__ n) {
    if (threadIdx.x == 0 && blockIdx.x == 0) {
        int is64 = 1;
        for (int i = 0; i < 64; i++) {
            long long v = n[i];
            if (v < 0 || v >= (long long)N_NODES) { is64 = 0; break; }
        }
        g_is64 = is64;
    }
}

__device__ __forceinline__ uint32_t smem_u32(const void* p) {
    uint32_t a;
    asm("{ .reg .u64 t; cvta.to.shared.u64 t, %1; cvt.u32.u64 %0, t; }" : "=r"(a) : "l"(p));
    return a;
}

#define BARX(id, cnt) asm volatile("bar.sync %0, %1;" :: "r"(id), "r"(cnt) : "memory")

#define LDSM_X4(r, addr) \
    asm volatile("ldmatrix.sync.aligned.m8n8.x4.shared.b16 {%0,%1,%2,%3}, [%4];" \
        : "=r"((r)[0]), "=r"((r)[1]), "=r"((r)[2]), "=r"((r)[3]) : "r"(addr))

#define LDSM_X4T(r, addr) \
    asm volatile("ldmatrix.sync.aligned.m8n8.x4.trans.shared.b16 {%0,%1,%2,%3}, [%4];" \
        : "=r"((r)[0]), "=r"((r)[1]), "=r"((r)[2]), "=r"((r)[3]) : "r"(addr))

#define MMA16816(ac, a, b0, b1) \
    asm volatile("mma.sync.aligned.m16n8k16.row.col.f32.bf16.bf16.f32 " \
        "{%0,%1,%2,%3}, {%4,%5,%6,%7}, {%8,%9}, {%0,%1,%2,%3};" \
        : "+f"((ac)[0]), "+f"((ac)[1]), "+f"((ac)[2]), "+f"((ac)[3]) \
        : "r"((a)[0]), "r"((a)[1]), "r"((a)[2]), "r"((a)[3]), "r"(b0), "r"(b1))

__device__ __forceinline__ unsigned short bf_hi(float x) {
    return __bfloat16_as_ushort(__float2bfloat16(x));
}
__device__ __forceinline__ unsigned short bf_lo(float x) {
    __nv_bfloat16 h = __float2bfloat16(x);
    return __bfloat16_as_ushort(__float2bfloat16(x - __bfloat162float(h)));
}
__device__ __forceinline__ uint32_t pack2(unsigned short a, unsigned short b) {
    return (uint32_t)a | ((uint32_t)b << 16);
}

// K=128 triple product (error-compensated): acc += Ah@Bh + Al@Bh + Ah@Bl
// Warp tile: 16 rows (r0) x 64 cols (c0).
__device__ __forceinline__ void run_product(
    float acc[8][4], uint32_t sAh, uint32_t sAl, uint32_t sBh, uint32_t sBl,
    int lane, int r0, int c0)
{
    const int arow = lane & 15;
    const int aka  = (lane >> 4) << 3;
    const int bk   = (lane & 7) + ((lane >> 3) & 1) * 8;
    const int bn   = ((lane >> 4) & 1) * 8;
    #pragma unroll
    for (int ks = 0; ks < 8; ks++) {
        const int k0 = ks * 16;
        uint32_t ah[4], al[4], bh[4][4], bl[4][4];
        {
            uint32_t off = (uint32_t)((r0 + arow) * ROWB + (k0 + aka) * 2);
            LDSM_X4(ah, sAh + off);
            LDSM_X4(al, sAl + off);
        }
        #pragma unroll
        for (int ng = 0; ng < 4; ng++) {
            uint32_t off = (uint32_t)((k0 + bk) * ROWB + (c0 + ng * 16 + bn) * 2);
            LDSM_X4T(bh[ng], sBh + off);
            LDSM_X4T(bl[ng], sBl + off);
        }
        #pragma unroll
        for (int nt = 0; nt < 8; nt++) {
            const int ng = nt >> 1, s2 = (nt & 1) * 2;
            MMA16816(acc[nt], ah, bh[ng][s2], bh[ng][s2 + 1]);
            MMA16816(acc[nt], al, bh[ng][s2], bh[ng][s2 + 1]);
            MMA16816(acc[nt], ah, bl[ng][s2], bl[ng][s2 + 1]);
        }
    }
}

// A tile: raw[row0+m][k0..k0+127] -> hi/lo bf16, by the 256 MMA threads
__device__ __forceinline__ void load_A_raw(char* sm, const float* __restrict__ raw,
                                           int row0, int valid, int k0, int tid) {
    #pragma unroll 2
    for (int i = tid; i < TM * 32; i += NMMA) {
        int m  = i >> 5;
        int k4 = (i & 31) << 2;
        float4 v = make_float4(0.f, 0.f, 0.f, 0.f);
        if (m < valid)
            v = *(const float4*)&raw[(size_t)(row0 + m) * RAW_DIM + k0 + k4];
        uint2 hp = make_uint2(pack2(bf_hi(v.x), bf_hi(v.y)), pack2(bf_hi(v.z), bf_hi(v.w)));
        uint2 lp = make_uint2(pack2(bf_lo(v.x), bf_lo(v.y)), pack2(bf_lo(v.z), bf_lo(v.w)));
        *(uint2*)(sm + OFF_AH + m * ROWB + k4 * 2) = hp;
        *(uint2*)(sm + OFF_AL + m * ROWB + k4 * 2) = lp;
    }
}

// B tile: W[k0+k][0..127] -> hi/lo bf16, by the 256 MMA threads
__device__ __forceinline__ void load_B_w(char* sm, const float* __restrict__ W,
                                         int k0, int tid) {
    #pragma unroll 2
    for (int i = tid; i < 128 * 32; i += NMMA) {
        int k  = i >> 5;
        int n4 = (i & 31) << 2;
        float4 v = *(const float4*)&W[(size_t)(k0 + k) * 128 + n4];
        uint2 hp = make_uint2(pack2(bf_hi(v.x), bf_hi(v.y)), pack2(bf_hi(v.z), bf_hi(v.w)));
        uint2 lp = make_uint2(pack2(bf_lo(v.x), bf_lo(v.y)), pack2(bf_lo(v.z), bf_lo(v.w)));
        *(uint2*)(sm + OFF_BH + k * ROWB + n4 * 2) = hp;
        *(uint2*)(sm + OFF_BL + k * ROWB + n4 * 2) = lp;
    }
}

extern __shared__ char sm[];

__global__ __launch_bounds__(THREADS, 1)
void fused_ws_kernel(
    const float* __restrict__ raw,
    const void*  __restrict__ neigh,
    const float* __restrict__ memory,
    const float* __restrict__ W1, const float* __restrict__ b1,
    const float* __restrict__ W2, const float* __restrict__ b2,
    const float* __restrict__ Wn, const float* __restrict__ bn,
    float*       __restrict__ out)
{
    const uint32_t smb = smem_u32(sm);
    const int tid  = threadIdx.x;
    const int lane = tid & 31;
    const int wid  = tid >> 5;
    const int row0 = blockIdx.x * TM;
    const int valid = min(TM, N_SRC - row0);

    if (tid == 0) *(int*)(sm + OFF_IS64) = g_is64;
    if (tid < 128) {
        ((float*)(sm + OFF_B1S))[tid] = b1[tid];
        ((float*)(sm + OFF_B2S))[tid] = b2[tid];
        ((float*)(sm + OFF_BNS))[tid] = bn[tid];
    }
    __syncthreads();

    // ---- neighbor indices -> smem (all threads) ----
    {
        int is64 = *(volatile int*)(sm + OFF_IS64);
        int* nbw = (int*)(sm + OFF_NEI);
        if (is64) {
            const long long* p = (const long long*)neigh;
            for (int i = tid; i < TM * N_NEIGH; i += THREADS) {
                int r = i / N_NEIGH, j = i - r * N_NEIGH;
                nbw[i] = (r < valid) ? (int)p[(size_t)(row0 + r) * N_NEIGH + j] : 0;
            }
        } else {
            const int* p = (const int*)neigh;
            for (int i = tid; i < TM * N_NEIGH; i += THREADS) {
                int r = i / N_NEIGH, j = i - r * N_NEIGH;
                nbw[i] = (r < valid) ? p[(size_t)(row0 + r) * N_NEIGH + j] : 0;
            }
        }
    }
    __syncthreads();

    const uint32_t AH = smb + OFF_AH, AL = smb + OFF_AL;
    const uint32_t BH = smb + OFF_BH, BL = smb + OFF_BL;

    if (wid < 8) {
        // ================== MMA warps (tid 0..255) ==================
        const int r0 = (wid >> 1) * 16;     // 16-row warp tile
        const int c0 = (wid & 1) * 64;      // 64-col warp tile

        float acc[8][4];
        #pragma unroll
        for (int nt = 0; nt < 8; nt++)
            #pragma unroll
            for (int e = 0; e < 4; e++) acc[nt][e] = 0.f;

        // ---- GEMM1: raw @ W1 (K=256, two chunks) ----
        load_A_raw(sm, raw, row0, valid, 0, tid);
        load_B_w(sm, W1, 0, tid);
        BARX(1, NMMA);
        run_product(acc, AH, AL, BH, BL, lane, r0, c0);
        BARX(1, NMMA);

        load_A_raw(sm, raw, row0, valid, 128, tid);
        load_B_w(sm, W1, 128, tid);
        BARX(1, NMMA);
        run_product(acc, AH, AL, BH, BL, lane, r0, c0);
        BARX(1, NMMA);

        // ---- epilogue 1: h = relu(C1 + b1) -> A hi/lo tiles ----
        {
            const float* sb1 = (const float*)(sm + OFF_B1S);
            const int qr = lane >> 2, qc = (lane & 3) * 2;
            #pragma unroll
            for (int nt = 0; nt < 8; nt++) {
                int R = r0 + qr;
                int C = c0 + nt * 8 + qc;
                float v0 = fmaxf(acc[nt][0] + sb1[C],     0.f);
                float v1 = fmaxf(acc[nt][1] + sb1[C + 1], 0.f);
                float v2 = fmaxf(acc[nt][2] + sb1[C],     0.f);
                float v3 = fmaxf(acc[nt][3] + sb1[C + 1], 0.f);
                *(uint32_t*)(sm + OFF_AH + R * ROWB + C * 2)       = pack2(bf_hi(v0), bf_hi(v1));
                *(uint32_t*)(sm + OFF_AL + R * ROWB + C * 2)       = pack2(bf_lo(v0), bf_lo(v1));
                *(uint32_t*)(sm + OFF_AH + (R + 8) * ROWB + C * 2) = pack2(bf_hi(v2), bf_hi(v3));
                *(uint32_t*)(sm + OFF_AL + (R + 8) * ROWB + C * 2) = pack2(bf_lo(v2), bf_lo(v3));
                acc[nt][0] = acc[nt][1] = acc[nt][2] = acc[nt][3] = 0.f;
            }
        }
        load_B_w(sm, W2, 0, tid);
        BARX(1, NMMA);

        // ---- GEMM2: h @ W2 ----
        run_product(acc, AH, AL, BH, BL, lane, r0, c0);

        BARX(2, THREADS);   // GEMM2 done reading A/B; join gather warps

        // ---- stage a = relu(C2 + b2); load Wn (gather warps write agg meanwhile) ----
        {
            const float* sb2 = (const float*)(sm + OFF_B2S);
            float* stg = (float*)(sm + OFF_STG);
            const int qc = (lane & 3) * 2;
            #pragma unroll
            for (int nt = 0; nt < 8; nt++) {
                int C = c0 + nt * 8 + qc;
                int base = nt * 4 * NMMA + tid;
                stg[base]            = fmaxf(acc[nt][0] + sb2[C],     0.f);
                stg[base + NMMA]     = fmaxf(acc[nt][1] + sb2[C + 1], 0.f);
                stg[base + 2 * NMMA] = fmaxf(acc[nt][2] + sb2[C],     0.f);
                stg[base + 3 * NMMA] = fmaxf(acc[nt][3] + sb2[C + 1], 0.f);
                acc[nt][0] = acc[nt][1] = acc[nt][2] = acc[nt][3] = 0.f;
            }
        }
        load_B_w(sm, Wn, 0, tid);

        BARX(3, THREADS);   // agg tiles + Wn tiles ready

        // ---- GEMM3: agg @ Wn ----
        run_product(acc, AH, AL, BH, BL, lane, r0, c0);

        // ---- final: out = a + relu(C3 + bn) ----
        {
            const float* sbn = (const float*)(sm + OFF_BNS);
            const float* stg = (const float*)(sm + OFF_STG);
            const int qr = lane >> 2, qc = (lane & 3) * 2;
            #pragma unroll
            for (int nt = 0; nt < 8; nt++) {
                int R = r0 + qr;
                int C = c0 + nt * 8 + qc;
                int base = nt * 4 * NMMA + tid;
                float o0 = stg[base]            + fmaxf(acc[nt][0] + sbn[C],     0.f);
                float o1 = stg[base + NMMA]     + fmaxf(acc[nt][1] + sbn[C + 1], 0.f);
                float o2 = stg[base + 2 * NMMA] + fmaxf(acc[nt][2] + sbn[C],     0.f);
                float o3 = stg[base + 3 * NMMA] + fmaxf(acc[nt][3] + sbn[C + 1], 0.f);
                if (R < valid)
                    *(float2*)&out[(size_t)(row0 + R) * MSG + C] = make_float2(o0, o1);
                if (R + 8 < valid)
                    *(float2*)&out[(size_t)(row0 + R + 8) * MSG + C] = make_float2(o2, o3);
            }
        }
    } else {
        // ================== gather warps (wid 8..11) ==================
        // Warp gw owns rows [gw*16, gw*16+16). One (row, neighbor) = one
        // coalesced 512B warp load (lane -> float4 of 4 columns). Sums held
        // in registers until GEMM2 releases the A tiles.
        const int gw = wid - 8;
        const int* nb = (const int*)(sm + OFF_NEI);
        const float4* mem4 = (const float4*)memory;

        float4 sums[16];
        #pragma unroll
        for (int r = 0; r < 16; r++) {
            const int row = gw * 16 + r;
            float4 s = make_float4(0.f, 0.f, 0.f, 0.f);
            #pragma unroll
            for (int j = 0; j < N_NEIGH; j++) {
                int nd = nb[row * N_NEIGH + j];
                float4 v = __ldg(&mem4[(size_t)nd * 32 + lane]);
                s.x += v.x; s.y += v.y; s.z += v.z; s.w += v.w;
            }
            const float inv = 1.0f / (float)N_NEIGH;
            s.x *= inv; s.y *= inv; s.z *= inv; s.w *= inv;
            sums[r] = s;
        }

        BARX(2, THREADS);   // wait for GEMM2 to finish reading A tiles

        #pragma unroll
        for (int r = 0; r < 16; r++) {
            const int row = gw * 16 + r;
            const int c = lane * 4;
            float4 s = sums[r];
            uint2 hp = make_uint2(pack2(bf_hi(s.x), bf_hi(s.y)), pack2(bf_hi(s.z), bf_hi(s.w)));
            uint2 lp = make_uint2(pack2(bf_lo(s.x), bf_lo(s.y)), pack2(bf_lo(s.z), bf_lo(s.w)));
            *(uint2*)(sm + OFF_AH + row * ROWB + c * 2) = hp;
            *(uint2*)(sm + OFF_AL + row * ROWB + c * 2) = lp;
        }

        BARX(3, THREADS);   // agg published; MMA warps run GEMM3
    }
}

extern "C" void kernel_launch(void* const* d_in, const int* in_sizes, int n_in,
                              void* d_out, int out_size) {
    const float* raw    = (const float*)d_in[0];
    const void*  neigh  = (const void*) d_in[1];
    const float* memory = (const float*)d_in[2];
    const float* W1     = (const float*)d_in[3];
    const float* b1     = (const float*)d_in[4];
    const float* W2     = (const float*)d_in[5];
    const float* b2     = (const float*)d_in[6];
    const float* Wn     = (const float*)d_in[7];
    const float* bn     = (const float*)d_in[8];
    float* out          = (float*)d_out;

    cudaFuncSetAttribute(fused_ws_kernel,
                         cudaFuncAttributeMaxDynamicSharedMemorySize, SMEM_REQ);

    detect_idx_kernel<<<1, 32>>>((const long long*)neigh);

    int nblocks = (N_SRC + TM - 1) / TM;   // 1563
    fused_ws_kernel<<<nblocks, THREADS, SMEM_REQ>>>(
        raw, neigh, memory, W1, b1, W2, b2, Wn, bn, out);
}

// round 6
// speedup vs baseline: 2.3818x; 1.2670x over previous
#include <cuda_runtime.h>
#include <cuda_bf16.h>
#include <cstdint>

#define N_SRC     100000
#define N_NODES   1000000
#define N_NEIGH   20
#define RAW_DIM   256
#define MSG       128

#define TM        32           // 100000 = 32 * 3125 exactly
#define THREADS   192          // 4 MMA warps + 2 gather warps
#define NMMA      128

// A tile: [32 rows][264 bf16] stride 528 B (33*16B -> ldmatrix conflict-free)
#define ASTR      528
// B tile: [128 k][136 bf16] stride 272 B (17*16B)
#define BSTR      272

#define OFF_AH    0                     // 32*528 = 16896
#define OFF_AL    16896                 // 16896  -> 33792
#define OFF_BH    33792                 // 128*272 = 34816 -> 68608
#define OFF_BL    68608                 // 34816  -> 103424
#define OFF_NEI   103424                // 32*20*4 = 2560 -> 105984
#define OFF_B1S   105984
#define OFF_B2S   106496
#define OFF_BNS   107008
#define OFF_IS64  107520
#define SMEM_REQ  107536

// pre-converted weights, laid out exactly like the smem B tiles
__device__ __align__(16) __nv_bfloat16 g_W1h[256 * 136];
__device__ __align__(16) __nv_bfloat16 g_W1l[256 * 136];
__device__ __align__(16) __nv_bfloat16 g_W2h[128 * 136];
__device__ __align__(16) __nv_bfloat16 g_W2l[128 * 136];
__device__ __align__(16) __nv_bfloat16 g_Wnh[128 * 136];
__device__ __align__(16) __nv_bfloat16 g_Wnl[128 * 136];

__device__ int g_is64;

__global__ void detect_idx_kernel(const long long* __restrict__ n) {
    if (threadIdx.x == 0 && blockIdx.x == 0) {
        int is64 = 1;
        for (int i = 0; i < 64; i++) {
            long long v = n[i];
            if (v < 0 || v >= (long long)N_NODES) { is64 = 0; break; }
        }
        g_is64 = is64;
    }
}

__device__ __forceinline__ unsigned short bf_hi(float x) {
    return __bfloat16_as_ushort(__float2bfloat16(x));
}
__device__ __forceinline__ unsigned short bf_lo(float x) {
    __nv_bfloat16 h = __float2bfloat16(x);
    return __bfloat16_as_ushort(__float2bfloat16(x - __bfloat162float(h)));
}
__device__ __forceinline__ uint32_t pack2(unsigned short a, unsigned short b) {
    return (uint32_t)a | ((uint32_t)b << 16);
}

__global__ void prep_weights(const float* __restrict__ W1,
                             const float* __restrict__ W2,
                             const float* __restrict__ Wn) {
    int i = blockIdx.x * blockDim.x + threadIdx.x;
    if (i < 256 * 128) {
        int r = i >> 7, c = i & 127;
        float v = W1[i];
        g_W1h[r * 136 + c] = __ushort_as_bfloat16(bf_hi(v));
        g_W1l[r * 136 + c] = __ushort_as_bfloat16(bf_lo(v));
    } else if (i < 256 * 128 + 128 * 128) {
        int j = i - 256 * 128;
        int r = j >> 7, c = j & 127;
        float v = W2[j];
        g_W2h[r * 136 + c] = __ushort_as_bfloat16(bf_hi(v));
        g_W2l[r * 136 + c] = __ushort_as_bfloat16(bf_lo(v));
    } else if (i < 256 * 128 + 2 * 128 * 128) {
        int j = i - 256 * 128 - 128 * 128;
        int r = j >> 7, c = j & 127;
        float v = Wn[j];
        g_Wnh[r * 136 + c] = __ushort_as_bfloat16(bf_hi(v));
        g_Wnl[r * 136 + c] = __ushort_as_bfloat16(bf_lo(v));
    }
}

__device__ __forceinline__ uint32_t smem_u32(const void* p) {
    uint32_t a;
    asm("{ .reg .u64 t; cvta.to.shared.u64 t, %1; cvt.u32.u64 %0, t; }" : "=r"(a) : "l"(p));
    return a;
}

#define BARX(id, cnt) asm volatile("bar.sync %0, %1;" :: "r"(id), "r"(cnt) : "memory")

#define LDSM_X4(r, addr) \
    asm volatile("ldmatrix.sync.aligned.m8n8.x4.shared.b16 {%0,%1,%2,%3}, [%4];" \
        : "=r"((r)[0]), "=r"((r)[1]), "=r"((r)[2]), "=r"((r)[3]) : "r"(addr))

#define LDSM_X4T(r, addr) \
    asm volatile("ldmatrix.sync.aligned.m8n8.x4.trans.shared.b16 {%0,%1,%2,%3}, [%4];" \
        : "=r"((r)[0]), "=r"((r)[1]), "=r"((r)[2]), "=r"((r)[3]) : "r"(addr))

#define MMA16816(ac, a, b0, b1) \
    asm volatile("mma.sync.aligned.m16n8k16.row.col.f32.bf16.bf16.f32 " \
        "{%0,%1,%2,%3}, {%4,%5,%6,%7}, {%8,%9}, {%0,%1,%2,%3};" \
        : "+f"((ac)[0]), "+f"((ac)[1]), "+f"((ac)[2]), "+f"((ac)[3]) \
        : "r"((a)[0]), "r"((a)[1]), "r"((a)[2]), "r"((a)[3]), "r"(b0), "r"(b1))

// K=128 error-compensated triple product: acc += Ah@Bh + Al@Bh + Ah@Bl
// Warp tile 16 rows (r0) x 64 cols (c0). A stride 528 B, col offset aoff elems.
__device__ __forceinline__ void run_product(
    float acc[8][4], uint32_t sAh, uint32_t sAl, uint32_t sBh, uint32_t sBl,
    int lane, int r0, int c0, int aoff)
{
    const int arow = lane & 15;
    const int aka  = (lane >> 4) << 3;
    const int bk   = (lane & 7) + ((lane >> 3) & 1) * 8;
    const int bn   = ((lane >> 4) & 1) * 8;
    #pragma unroll
    for (int ks = 0; ks < 8; ks++) {
        const int k0 = ks * 16;
        uint32_t ah[4], al[4], bh[4][4], bl[4][4];
        {
            uint32_t off = (uint32_t)((r0 + arow) * ASTR + (aoff + k0 + aka) * 2);
            LDSM_X4(ah, sAh + off);
            LDSM_X4(al, sAl + off);
        }
        #pragma unroll
        for (int ng = 0; ng < 4; ng++) {
            uint32_t off = (uint32_t)((k0 + bk) * BSTR + (c0 + ng * 16 + bn) * 2);
            LDSM_X4T(bh[ng], sBh + off);
            LDSM_X4T(bl[ng], sBl + off);
        }
        #pragma unroll
        for (int nt = 0; nt < 8; nt++) {
            const int ng = nt >> 1, s2 = (nt & 1) * 2;
            MMA16816(acc[nt], ah, bh[ng][s2], bh[ng][s2 + 1]);
            MMA16816(acc[nt], al, bh[ng][s2], bh[ng][s2 + 1]);
            MMA16816(acc[nt], ah, bl[ng][s2], bl[ng][s2 + 1]);
        }
    }
}

// full-K A tile: raw[row0+m][0..255] -> hi/lo bf16, by 128 MMA threads
__device__ __forceinline__ void load_A_full(char* sm, const float* __restrict__ raw,
                                            int row0, int tid) {
    #pragma unroll 4
    for (int i = tid; i < TM * 64; i += NMMA) {
        int m  = i >> 6;
        int k4 = (i & 63) << 2;
        float4 v = *(const float4*)&raw[(size_t)(row0 + m) * RAW_DIM + k4];
        uint2 hp = make_uint2(pack2(bf_hi(v.x), bf_hi(v.y)), pack2(bf_hi(v.z), bf_hi(v.w)));
        uint2 lp = make_uint2(pack2(bf_lo(v.x), bf_lo(v.y)), pack2(bf_lo(v.z), bf_lo(v.w)));
        *(uint2*)(sm + OFF_AH + m * ASTR + k4 * 2) = hp;
        *(uint2*)(sm + OFF_AL + m * ASTR + k4 * 2) = lp;
    }
}

// B tile: pure 16B copies from pre-converted weights (no conversion ALU)
__device__ __forceinline__ void load_B_pre(char* sm,
                                           const __nv_bfloat16* __restrict__ gh,
                                           const __nv_bfloat16* __restrict__ gl,
                                           int k0, int tid) {
    const uint4* sh = (const uint4*)(gh + k0 * 136);
    const uint4* sl = (const uint4*)(gl + k0 * 136);
    #pragma unroll 4
    for (int i = tid; i < 2176; i += NMMA) {   // 128*272/16
        *(uint4*)(sm + OFF_BH + i * 16) = __ldg(&sh[i]);
        *(uint4*)(sm + OFF_BL + i * 16) = __ldg(&sl[i]);
    }
}

// fp32 'a' staging in the unused upper-K bytes (256..511) of the A tiles
__device__ __forceinline__ uint32_t stg_addr(int li) {
    return (uint32_t)(((li >> 11) ? OFF_AL : OFF_AH)
                      + ((li >> 6) & 31) * ASTR + 256 + (li & 63) * 4);
}

extern __shared__ char sm[];

__global__ __launch_bounds__(THREADS, 2)
void fused_ws2_kernel(
    const float* __restrict__ raw,
    const void*  __restrict__ neigh,
    const float* __restrict__ memory,
    const float* __restrict__ b1,
    const float* __restrict__ b2,
    const float* __restrict__ bn,
    float*       __restrict__ out)
{
    const uint32_t smb = smem_u32(sm);
    const int tid  = threadIdx.x;
    const int lane = tid & 31;
    const int wid  = tid >> 5;
    const int row0 = blockIdx.x * TM;

    if (tid == 0) *(int*)(sm + OFF_IS64) = g_is64;
    if (tid < 128) {
        ((float*)(sm + OFF_B1S))[tid] = b1[tid];
        ((float*)(sm + OFF_B2S))[tid] = b2[tid];
        ((float*)(sm + OFF_BNS))[tid] = bn[tid];
    }
    __syncthreads();

    // ---- neighbor indices -> smem (all threads) ----
    {
        int is64 = *(volatile int*)(sm + OFF_IS64);
        int* nbw = (int*)(sm + OFF_NEI);
        if (is64) {
            const long long* p = (const long long*)neigh;
            for (int i = tid; i < TM * N_NEIGH; i += THREADS)
                nbw[i] = (int)p[(size_t)row0 * N_NEIGH + i];
        } else {
            const int* p = (const int*)neigh;
            for (int i = tid; i < TM * N_NEIGH; i += THREADS)
                nbw[i] = p[(size_t)row0 * N_NEIGH + i];
        }
    }
    __syncthreads();

    const uint32_t AH = smb + OFF_AH, AL = smb + OFF_AL;
    const uint32_t BH = smb + OFF_BH, BL = smb + OFF_BL;

    if (wid < 4) {
        // ================== MMA warps (tid 0..127) ==================
        const int r0 = (wid >> 1) * 16;
        const int c0 = (wid & 1) * 64;

        float acc[8][4];
        #pragma unroll
        for (int nt = 0; nt < 8; nt++)
            #pragma unroll
            for (int e = 0; e < 4; e++) acc[nt][e] = 0.f;

        // ---- GEMM1: raw @ W1 (full A prefetch, B in two L2 chunks) ----
        load_A_full(sm, raw, row0, tid);
        load_B_pre(sm, g_W1h, g_W1l, 0, tid);
        BARX(1, NMMA);
        run_product(acc, AH, AL, BH, BL, lane, r0, c0, 0);
        BARX(1, NMMA);
        load_B_pre(sm, g_W1h, g_W1l, 128, tid);
        BARX(1, NMMA);
        run_product(acc, AH, AL, BH, BL, lane, r0, c0, 128);
        BARX(1, NMMA);

        // ---- epilogue 1: h = relu(C1 + b1) -> A cols 0..127 ----
        {
            const float* sb1 = (const float*)(sm + OFF_B1S);
            const int qr = lane >> 2, qc = (lane & 3) * 2;
            #pragma unroll
            for (int nt = 0; nt < 8; nt++) {
                int R = r0 + qr;
                int C = c0 + nt * 8 + qc;
                float v0 = fmaxf(acc[nt][0] + sb1[C],     0.f);
                float v1 = fmaxf(acc[nt][1] + sb1[C + 1], 0.f);
                float v2 = fmaxf(acc[nt][2] + sb1[C],     0.f);
                float v3 = fmaxf(acc[nt][3] + sb1[C + 1], 0.f);
                *(uint32_t*)(sm + OFF_AH + R * ASTR + C * 2)       = pack2(bf_hi(v0), bf_hi(v1));
                *(uint32_t*)(sm + OFF_AL + R * ASTR + C * 2)       = pack2(bf_lo(v0), bf_lo(v1));
                *(uint32_t*)(sm + OFF_AH + (R + 8) * ASTR + C * 2) = pack2(bf_hi(v2), bf_hi(v3));
                *(uint32_t*)(sm + OFF_AL + (R + 8) * ASTR + C * 2) = pack2(bf_lo(v2), bf_lo(v3));
                acc[nt][0] = acc[nt][1] = acc[nt][2] = acc[nt][3] = 0.f;
            }
        }
        load_B_pre(sm, g_W2h, g_W2l, 0, tid);
        BARX(1, NMMA);

        // ---- GEMM2: h @ W2 ----
        run_product(acc, AH, AL, BH, BL, lane, r0, c0, 0);

        BARX(2, THREADS);   // A tiles free for agg; gather sums ready

        // ---- stage a = relu(C2 + b2) into upper-K bytes; load Wn ----
        {
            const float* sb2 = (const float*)(sm + OFF_B2S);
            const int qc = (lane & 3) * 2;
            #pragma unroll
            for (int nt = 0; nt < 8; nt++) {
                int C = c0 + nt * 8 + qc;
                *(float*)(sm + stg_addr((nt * 4 + 0) * NMMA + tid)) = fmaxf(acc[nt][0] + sb2[C],     0.f);
                *(float*)(sm + stg_addr((nt * 4 + 1) * NMMA + tid)) = fmaxf(acc[nt][1] + sb2[C + 1], 0.f);
                *(float*)(sm + stg_addr((nt * 4 + 2) * NMMA + tid)) = fmaxf(acc[nt][2] + sb2[C],     0.f);
                *(float*)(sm + stg_addr((nt * 4 + 3) * NMMA + tid)) = fmaxf(acc[nt][3] + sb2[C + 1], 0.f);
                acc[nt][0] = acc[nt][1] = acc[nt][2] = acc[nt][3] = 0.f;
            }
        }
        load_B_pre(sm, g_Wnh, g_Wnl, 0, tid);

        BARX(3, THREADS);   // agg + Wn ready

        // ---- GEMM3: agg @ Wn ----
        run_product(acc, AH, AL, BH, BL, lane, r0, c0, 0);

        // ---- final: out = a + relu(C3 + bn) ----
        {
            const float* sbn = (const float*)(sm + OFF_BNS);
            const int qr = lane >> 2, qc = (lane & 3) * 2;
            #pragma unroll
            for (int nt = 0; nt < 8; nt++) {
                int R = r0 + qr;
                int C = c0 + nt * 8 + qc;
                float a0 = *(const float*)(sm + stg_addr((nt * 4 + 0) * NMMA + tid));
                float a1 = *(const float*)(sm + stg_addr((nt * 4 + 1) * NMMA + tid));
                float a2 = *(const float*)(sm + stg_addr((nt * 4 + 2) * NMMA + tid));
                float a3 = *(const float*)(sm + stg_addr((nt * 4 + 3) * NMMA + tid));
                float o0 = a0 + fmaxf(acc[nt][0] + sbn[C],     0.f);
                float o1 = a1 + fmaxf(acc[nt][1] + sbn[C + 1], 0.f);
                float o2 = a2 + fmaxf(acc[nt][2] + sbn[C],     0.f);
                float o3 = a3 + fmaxf(acc[nt][3] + sbn[C + 1], 0.f);
                *(float2*)&out[(size_t)(row0 + R) * MSG + C]     = make_float2(o0, o1);
                *(float2*)&out[(size_t)(row0 + R + 8) * MSG + C] = make_float2(o2, o3);
            }
        }
    } else {
        // ================== gather warps (wid 4,5) ==================
        const int gw = wid - 4;
        const int* nb = (const int*)(sm + OFF_NEI);
        const float4* mem4 = (const float4*)memory;

        float4 sums[16];
        #pragma unroll
        for (int r = 0; r < 16; r++) {
            const int row = gw * 16 + r;
            float4 s = make_float4(0.f, 0.f, 0.f, 0.f);
            #pragma unroll
            for (int j = 0; j < N_NEIGH; j++) {
                int nd = nb[row * N_NEIGH + j];
                float4 v = __ldg(&mem4[(size_t)nd * 32 + lane]);
                s.x += v.x; s.y += v.y; s.z += v.z; s.w += v.w;
            }
            const float inv = 1.0f / (float)N_NEIGH;
            s.x *= inv; s.y *= inv; s.z *= inv; s.w *= inv;
            sums[r] = s;
        }

        BARX(2, THREADS);   // wait until GEMM2 stops reading A tiles

        #pragma unroll
        for (int r = 0; r < 16; r++) {
            const int row = gw * 16 + r;
            const int c = lane * 4;
            float4 s = sums[r];
            uint2 hp = make_uint2(pack2(bf_hi(s.x), bf_hi(s.y)), pack2(bf_hi(s.z), bf_hi(s.w)));
            uint2 lp = make_uint2(pack2(bf_lo(s.x), bf_lo(s.y)), pack2(bf_lo(s.z), bf_lo(s.w)));
            *(uint2*)(sm + OFF_AH + row * ASTR + c * 2) = hp;
            *(uint2*)(sm + OFF_AL + row * ASTR + c * 2) = lp;
        }

        BARX(3, THREADS);   // agg published; MMA warps run GEMM3
    }
}

extern "C" void kernel_launch(void* const* d_in, const int* in_sizes, int n_in,
                              void* d_out, int out_size) {
    const float* raw    = (const float*)d_in[0];
    const void*  neigh  = (const void*) d_in[1];
    const float* memory = (const float*)d_in[2];
    const float* W1     = (const float*)d_in[3];
    const float* b1     = (const float*)d_in[4];
    const float* W2     = (const float*)d_in[5];
    const float* b2     = (const float*)d_in[6];
    const float* Wn     = (const float*)d_in[7];
    const float* bn     = (const float*)d_in[8];
    float* out          = (float*)d_out;

    cudaFuncSetAttribute(fused_ws2_kernel,
                         cudaFuncAttributeMaxDynamicSharedMemorySize, SMEM_REQ);

    detect_idx_kernel<<<1, 32>>>((const long long*)neigh);
    prep_weights<<<256, 256>>>(W1, W2, Wn);

    int nblocks = N_SRC / TM;   // 3125 exact
    fused_ws2_kernel<<<nblocks, THREADS, SMEM_REQ>>>(
        raw, neigh, memory, b1, b2, bn, out);
}